// round 14
// baseline (speedup 1.0000x reference)
#include <cuda_runtime.h>
#include <math.h>

typedef unsigned long long ull;

// ---------------------------------------------------------------------------
// Net_47132971107101: fake-quant CNN forward
//   conv1 fp32: vertical f32x2 pairs in merged smem array -> 6 LDS.128 patch
//     loads per pooled output; weights streamed (broadcast LDS).
//   conv2 dp4a: weights stride-12 in smem -> 3 vector LDS per task.
//   FC dp4a: weights stride-52 -> 13 int4 __ldg.
// 2 images per 256-thread block, 5 blocks/SM.
// ---------------------------------------------------------------------------

__device__ __align__(16) ull g_w1d[48];     // ch*12 + ky*4 + kx (kx<3), (w,w) f32x2; pad=0
__device__ __align__(16) int g_w2pack[48];  // ch*12 + tap (tap<9), 4 in-ch int8; pad=0
__device__ __align__(16) int g_wfpack[520]; // o*52 + pp (pp<49); pad=0
__device__ float g_s2v;
__device__ float g_sf2;

__global__ void prep_kernel(const float* __restrict__ w1,
                            const float* __restrict__ w2,
                            const float* __restrict__ wf) {
    __shared__ float red[256];
    const int t = threadIdx.x;

    float m = 0.f;
    for (int i = t; i < 36; i += 256) m = fmaxf(m, fabsf(w1[i]));
    red[t] = m; __syncthreads();
    for (int s = 128; s > 0; s >>= 1) { if (t < s) red[t] = fmaxf(red[t], red[t+s]); __syncthreads(); }
    const float s1 = red[0]; __syncthreads();

    m = 0.f;
    for (int i = t; i < 144; i += 256) m = fmaxf(m, fabsf(w2[i]));
    red[t] = m; __syncthreads();
    for (int s = 128; s > 0; s >>= 1) { if (t < s) red[t] = fmaxf(red[t], red[t+s]); __syncthreads(); }
    const float s2 = red[0]; __syncthreads();

    m = 0.f;
    for (int i = t; i < 1960; i += 256) m = fmaxf(m, fabsf(wf[i]));
    red[t] = m; __syncthreads();
    for (int s = 128; s > 0; s >>= 1) { if (t < s) red[t] = fmaxf(red[t], red[t+s]); __syncthreads(); }
    const float sf = red[0];

    // w1: slot = ch*12 + ky*4 + kx (kx<3), (w,w) f32x2 pairs, pad 0
    if (t < 48) {
        const int ch = t / 12, r = t % 12, ky = r / 4, kx = r % 4;
        ull val = 0ull;
        if (kx < 3) {
            float q = fminf(fmaxf(rintf(w1[ch*9 + ky*3 + kx] / s1), -1.f), 1.f);
            float w = 0.5f * s1 * q;
            unsigned int u; memcpy(&u, &w, 4);
            val = ((ull)u << 32) | (ull)u;
        }
        g_w1d[t] = val;
    }
    // w2: slot = ch*12 + tap (tap<9), pad 0
    if (t < 48) {
        const int o = t / 12, tap = t % 12;
        int pack = 0;
        if (tap < 9) {
            #pragma unroll
            for (int i = 0; i < 4; i++) {
                float q = fminf(fmaxf(rintf(w2[o*36 + i*9 + tap] / s2), -1.f), 1.f);
                pack |= (((int)q) & 0xFF) << (8 * i);
            }
        }
        g_w2pack[t] = pack;
    }
    // wf: slot = o*52 + pp (pp<49) packs the 4 channel values at spatial pp
    for (int i = t; i < 520; i += 256) {
        const int o = i / 52, pp = i % 52;
        int pack = 0;
        if (pp < 49) {
            #pragma unroll
            for (int j = 0; j < 4; j++) {
                float q = fminf(fmaxf(rintf(wf[o*196 + j*49 + pp] / sf), -1.f), 1.f);
                pack |= (((int)q) & 0xFF) << (8 * j);
            }
        }
        g_wfpack[i] = pack;
    }
    if (t == 0) { g_s2v = s2; g_sf2 = 2.f * sf; }
}

__device__ __forceinline__ void f2up(ull v, float& lo, float& hi) {
    asm("mov.b64 {%0,%1}, %2;" : "=f"(lo), "=f"(hi) : "l"(v));
}
__device__ __forceinline__ ull ffma2(ull a, ull b, ull c) {
    ull d; asm("fma.rn.f32x2 %0, %1, %2, %3;" : "=l"(d) : "l"(a), "l"(b), "l"(c)); return d;
}

#define TPB 256

__global__ void __launch_bounds__(TPB, 5)
net_kernel(const float* __restrict__ x, float* __restrict__ out) {
    // s_pair[img][r][c]: vertical pair (pad_row r, pad_row r+1) at padded col c.
    // r in 0..28, c in 0..29. Row stride 30 ull = 240 B (16B-aligned).
    __shared__ __align__(16) ull s_pair[2][29][30];     // 13920 B
    __shared__ __align__(16) int a1p[2][16 * 16];       // padded 14x14, 4ch bytes
    __shared__ __align__(16) int a2w[2][52];
    __shared__ __align__(16) ull s_w1[48];
    __shared__ __align__(16) int s_w2[48];

    const int t = threadIdx.x;
    const long long b0 = (long long)blockIdx.x * 2;

    // ---- phase 0: border zeroing + weights -------------------------------
    if (t < 48) { s_w1[t] = g_w1d[t]; s_w2[t] = g_w2pack[t]; }
    if (t < 236) {               // s_pair borders: 118 cells per image
        const int gi = t / 118, j = t % 118;
        if (j < 30)       { ((float*)&s_pair[gi][0][j])[0] = 0.f; }        // row0 lo
        else if (j < 60)  { ((float*)&s_pair[gi][28][j - 30])[1] = 0.f; }  // row28 hi
        else if (j < 89)  { s_pair[gi][j - 60][0] = 0ull; }                // col 0
        else              { s_pair[gi][j - 89][29] = 0ull; }               // col 29
    }
    if (t < 120) {               // a1p borders: 60 cells per image
        int gi = t / 60, j = t % 60, y, c;
        if (j < 16)      { y = 0;          c = j; }
        else if (j < 32) { y = 15;         c = j - 16; }
        else if (j < 46) { y = j - 32 + 1; c = 0; }
        else             { y = j - 46 + 1; c = 15; }
        a1p[gi][y * 16 + c] = 0;
    }
    if (t < 6) a2w[t / 3][49 + (t % 3)] = 0;  // pad for int4 FC reads
    __syncthreads();

    // ---- phase 1: load x into vertical-pair array ------------------------
    // img row y col c (padded col c+1): hi of entry [y][c+1], lo of [y+1][c+1]
    for (int i = t; i < 392; i += TPB) {
        const int gi = i / 196, q = i % 196;
        float4 v = ((const float4*)(x + (b0 + gi) * 784))[q];
        const int p = q * 4, y = p / 28, c = p % 28;   // c multiple of 4
        float* h;
        h = (float*)&s_pair[gi][y][c + 1];     h[1] = v.x;
        h = (float*)&s_pair[gi][y + 1][c + 1]; h[0] = v.x;
        h = (float*)&s_pair[gi][y][c + 2];     h[1] = v.y;
        h = (float*)&s_pair[gi][y + 1][c + 2]; h[0] = v.y;
        h = (float*)&s_pair[gi][y][c + 3];     h[1] = v.z;
        h = (float*)&s_pair[gi][y + 1][c + 3]; h[0] = v.z;
        h = (float*)&s_pair[gi][y][c + 4];     h[1] = v.w;
        h = (float*)&s_pair[gi][y + 1][c + 4]; h[0] = v.w;
    }
    __syncthreads();

    // ---- phase 2: conv1 + pool + quant; 1 pooled output per task ---------
    for (int task = t; task < 392; task += TPB) {
        const int gi = task / 196, v = task % 196;
        const int py = v / 14, px = v % 14;

        ull V[3][4];
        #pragma unroll
        for (int ky = 0; ky < 3; ky++) {
            const int r = 2 * py + ky;
            ulonglong2 p01 = *(const ulonglong2*)&s_pair[gi][r][2 * px];
            ulonglong2 p23 = *(const ulonglong2*)&s_pair[gi][r][2 * px + 2];
            V[ky][0] = p01.x; V[ky][1] = p01.y; V[ky][2] = p23.x; V[ky][3] = p23.y;
        }

        int pk = 0;
        #pragma unroll
        for (int ch = 0; ch < 4; ch++) {
            ull a0 = 0ull, a1 = 0ull;
            #pragma unroll
            for (int ky = 0; ky < 3; ky++) {
                const ulonglong2 w01 = *(const ulonglong2*)&s_w1[ch * 12 + ky * 4];
                const ull w2 = s_w1[ch * 12 + ky * 4 + 2];
                a0 = ffma2(V[ky][0], w01.x, a0);
                a0 = ffma2(V[ky][1], w01.y, a0);
                a0 = ffma2(V[ky][2], w2,    a0);
                a1 = ffma2(V[ky][1], w01.x, a1);
                a1 = ffma2(V[ky][2], w01.y, a1);
                a1 = ffma2(V[ky][3], w2,    a1);
            }
            float t0, bo0, t1, bo1;
            f2up(a0, t0, bo0); f2up(a1, t1, bo1);
            const float mx = fmaxf(fmaxf(t0, bo0), fmaxf(t1, bo1));
            const int a = min(max(__float2int_rn(mx), 0), 3);
            pk |= a << (8 * ch);
        }
        a1p[gi][(py + 1) * 16 + px + 1] = pk;
    }
    __syncthreads();

    // ---- phase 3: conv2 + pool + quant; (img, ch-pair, spatial) tasks ----
    if (t < 196) {
        const int gi = t / 98, v = t % 98;
        const int cp = v / 49, pp = v % 49;
        const int py = pp / 7, px = pp % 7;
        int q[4][4];
        #pragma unroll
        for (int r = 0; r < 4; r++) {
            int2 v0 = *(const int2*)&a1p[gi][(2 * py + r) * 16 + 2 * px];
            int2 v1 = *(const int2*)&a1p[gi][(2 * py + r) * 16 + 2 * px + 2];
            q[r][0] = v0.x; q[r][1] = v0.y; q[r][2] = v1.x; q[r][3] = v1.y;
        }
        const float s2v = g_s2v;
        unsigned int hv = 0;
        #pragma unroll
        for (int c2 = 0; c2 < 2; c2++) {
            const int ch = cp * 2 + c2;
            const int4 wA = *(const int4*)&s_w2[ch * 12];
            const int4 wB = *(const int4*)&s_w2[ch * 12 + 4];
            const int  w8 = s_w2[ch * 12 + 8];
            int wv[9];
            wv[0] = wA.x; wv[1] = wA.y; wv[2] = wA.z; wv[3] = wA.w;
            wv[4] = wB.x; wv[5] = wB.y; wv[6] = wB.z; wv[7] = wB.w;
            wv[8] = w8;
            int mx = -2147483647;
            #pragma unroll
            for (int wy = 0; wy < 2; wy++)
                #pragma unroll
                for (int wx = 0; wx < 2; wx++) {
                    int acc = 0;
                    #pragma unroll
                    for (int ky = 0; ky < 3; ky++)
                        #pragma unroll
                        for (int kx = 0; kx < 3; kx++)
                            acc = __dp4a(q[wy + ky][wx + kx], wv[ky * 3 + kx], acc);
                    mx = max(mx, acc);
                }
            const int a = min(max(__float2int_rn(s2v * (float)mx), 0), 3);
            hv |= (unsigned int)a << (8 * c2);
        }
        *(unsigned short*)((char*)&a2w[gi][0] + pp * 4 + cp * 2) = (unsigned short)hv;
    }
    __syncthreads();

    // ---- phase 4: FC, 20 tasks, 13 int4 weight loads ---------------------
    if (t < 20) {
        const int gi = t / 10, o = t % 10;
        int acc = 0;
        const int4* wf4 = (const int4*)&g_wfpack[o * 52];
        #pragma unroll
        for (int j = 0; j < 13; j++) {
            int4 va = *(const int4*)&a2w[gi][4 * j];   // pads 49..51 are 0
            int4 wb = __ldg(wf4 + j);                  // pads are 0
            acc = __dp4a(va.x, wb.x, acc);
            acc = __dp4a(va.y, wb.y, acc);
            acc = __dp4a(va.z, wb.z, acc);
            acc = __dp4a(va.w, wb.w, acc);
        }
        out[(b0 + gi) * 10 + o] = g_sf2 * (float)acc;
    }
}

extern "C" void kernel_launch(void* const* d_in, const int* in_sizes, int n_in,
                              void* d_out, int out_size) {
    const float* x  = (const float*)d_in[0];
    const float* w1 = (const float*)d_in[1];
    const float* w2 = (const float*)d_in[2];
    const float* wf = (const float*)d_in[3];
    float* out = (float*)d_out;
    const int B = in_sizes[0] / 784;

    prep_kernel<<<1, 256>>>(w1, w2, wf);
    net_kernel<<<B / 2, TPB>>>(x, out);
}

// round 15
// speedup vs baseline: 1.1173x; 1.1173x over previous
#include <cuda_runtime.h>
#include <math.h>

typedef unsigned long long ull;

// ---------------------------------------------------------------------------
// Net_47132971107101: fake-quant CNN forward
//   conv1 fp32: vertical f32x2 pairs in smem (6 LDS.128 patch loads/output);
//     weights read through the CONSTANT port (LDC/LDCU) -> off the smem crossbar.
//   conv2 dp4a: weights via constant port too (<=2-way divergent).
//   FC dp4a: weights stride-52 -> 13 int4 __ldg.
// Weights staged by prep_kernel in __device__, copied to __constant__ via a
// captured D2D cudaMemcpyAsync (explicitly allowed by the harness).
// 2 images per 256-thread block, 5 blocks/SM.
// ---------------------------------------------------------------------------

struct __align__(16) WBlob {
    ull   w1[48];   // ch*12 + ky*4 + kx (kx<3), (w,w) f32x2 pairs; pad=0
    int   w2[48];   // ch*12 + tap (tap<9), 4 in-ch int8 per word; pad=0
    float s2;       // conv2 scale
    float sf2;      // 2*sf
};

__device__   WBlob g_blob;          // staging (written by prep_kernel)
__constant__ WBlob c_blob;          // read by net_kernel via constant port
__device__ __align__(16) int g_wfpack[520]; // o*52 + pp (pp<49); pad=0

__global__ void prep_kernel(const float* __restrict__ w1,
                            const float* __restrict__ w2,
                            const float* __restrict__ wf) {
    __shared__ float red[256];
    const int t = threadIdx.x;

    float m = 0.f;
    for (int i = t; i < 36; i += 256) m = fmaxf(m, fabsf(w1[i]));
    red[t] = m; __syncthreads();
    for (int s = 128; s > 0; s >>= 1) { if (t < s) red[t] = fmaxf(red[t], red[t+s]); __syncthreads(); }
    const float s1 = red[0]; __syncthreads();

    m = 0.f;
    for (int i = t; i < 144; i += 256) m = fmaxf(m, fabsf(w2[i]));
    red[t] = m; __syncthreads();
    for (int s = 128; s > 0; s >>= 1) { if (t < s) red[t] = fmaxf(red[t], red[t+s]); __syncthreads(); }
    const float s2 = red[0]; __syncthreads();

    m = 0.f;
    for (int i = t; i < 1960; i += 256) m = fmaxf(m, fabsf(wf[i]));
    red[t] = m; __syncthreads();
    for (int s = 128; s > 0; s >>= 1) { if (t < s) red[t] = fmaxf(red[t], red[t+s]); __syncthreads(); }
    const float sf = red[0];

    // w1: slot = ch*12 + ky*4 + kx (kx<3), (w,w) f32x2 pairs, pad 0
    if (t < 48) {
        const int ch = t / 12, r = t % 12, ky = r / 4, kx = r % 4;
        ull val = 0ull;
        if (kx < 3) {
            float q = fminf(fmaxf(rintf(w1[ch*9 + ky*3 + kx] / s1), -1.f), 1.f);
            float w = 0.5f * s1 * q;
            unsigned int u; memcpy(&u, &w, 4);
            val = ((ull)u << 32) | (ull)u;
        }
        g_blob.w1[t] = val;
    }
    // w2: slot = ch*12 + tap (tap<9), pad 0
    if (t < 48) {
        const int o = t / 12, tap = t % 12;
        int pack = 0;
        if (tap < 9) {
            #pragma unroll
            for (int i = 0; i < 4; i++) {
                float q = fminf(fmaxf(rintf(w2[o*36 + i*9 + tap] / s2), -1.f), 1.f);
                pack |= (((int)q) & 0xFF) << (8 * i);
            }
        }
        g_blob.w2[t] = pack;
    }
    // wf: slot = o*52 + pp (pp<49) packs the 4 channel values at spatial pp
    for (int i = t; i < 520; i += 256) {
        const int o = i / 52, pp = i % 52;
        int pack = 0;
        if (pp < 49) {
            #pragma unroll
            for (int j = 0; j < 4; j++) {
                float q = fminf(fmaxf(rintf(wf[o*196 + j*49 + pp] / sf), -1.f), 1.f);
                pack |= (((int)q) & 0xFF) << (8 * j);
            }
        }
        g_wfpack[i] = pack;
    }
    if (t == 0) { g_blob.s2 = s2; g_blob.sf2 = 2.f * sf; }
}

__device__ __forceinline__ void f2up(ull v, float& lo, float& hi) {
    asm("mov.b64 {%0,%1}, %2;" : "=f"(lo), "=f"(hi) : "l"(v));
}
__device__ __forceinline__ ull ffma2(ull a, ull b, ull c) {
    ull d; asm("fma.rn.f32x2 %0, %1, %2, %3;" : "=l"(d) : "l"(a), "l"(b), "l"(c)); return d;
}

#define TPB 256

__global__ void __launch_bounds__(TPB, 5)
net_kernel(const float* __restrict__ x, float* __restrict__ out) {
    // s_pair[img][r][c]: vertical pair (pad_row r, pad_row r+1) at padded col c.
    __shared__ __align__(16) ull s_pair[2][29][30];     // 13920 B
    __shared__ __align__(16) int a1p[2][16 * 16];
    __shared__ __align__(16) int a2w[2][52];

    const int t = threadIdx.x;
    const long long b0 = (long long)blockIdx.x * 2;

    // ---- phase 0: border zeroing -----------------------------------------
    if (t < 236) {               // s_pair borders: 118 cells per image
        const int gi = t / 118, j = t % 118;
        if (j < 30)       { ((float*)&s_pair[gi][0][j])[0] = 0.f; }        // row0 lo
        else if (j < 60)  { ((float*)&s_pair[gi][28][j - 30])[1] = 0.f; }  // row28 hi
        else if (j < 89)  { s_pair[gi][j - 60][0] = 0ull; }                // col 0
        else              { s_pair[gi][j - 89][29] = 0ull; }               // col 29
    }
    if (t < 120) {               // a1p borders: 60 cells per image
        int gi = t / 60, j = t % 60, y, c;
        if (j < 16)      { y = 0;          c = j; }
        else if (j < 32) { y = 15;         c = j - 16; }
        else if (j < 46) { y = j - 32 + 1; c = 0; }
        else             { y = j - 46 + 1; c = 15; }
        a1p[gi][y * 16 + c] = 0;
    }
    if (t < 6) a2w[t / 3][49 + (t % 3)] = 0;  // pad for int4 FC reads
    __syncthreads();

    // ---- phase 1: load x into vertical-pair array ------------------------
    for (int i = t; i < 392; i += TPB) {
        const int gi = i / 196, q = i % 196;
        float4 v = ((const float4*)(x + (b0 + gi) * 784))[q];
        const int p = q * 4, y = p / 28, c = p % 28;   // c multiple of 4
        float* h;
        h = (float*)&s_pair[gi][y][c + 1];     h[1] = v.x;
        h = (float*)&s_pair[gi][y + 1][c + 1]; h[0] = v.x;
        h = (float*)&s_pair[gi][y][c + 2];     h[1] = v.y;
        h = (float*)&s_pair[gi][y + 1][c + 2]; h[0] = v.y;
        h = (float*)&s_pair[gi][y][c + 3];     h[1] = v.z;
        h = (float*)&s_pair[gi][y + 1][c + 3]; h[0] = v.z;
        h = (float*)&s_pair[gi][y][c + 4];     h[1] = v.w;
        h = (float*)&s_pair[gi][y + 1][c + 4]; h[0] = v.w;
    }
    __syncthreads();

    // ---- phase 2: conv1 + pool + quant; weights via constant port --------
    for (int task = t; task < 392; task += TPB) {
        const int gi = task / 196, v = task % 196;
        const int py = v / 14, px = v % 14;

        ull V[3][4];
        #pragma unroll
        for (int ky = 0; ky < 3; ky++) {
            const int r = 2 * py + ky;
            ulonglong2 p01 = *(const ulonglong2*)&s_pair[gi][r][2 * px];
            ulonglong2 p23 = *(const ulonglong2*)&s_pair[gi][r][2 * px + 2];
            V[ky][0] = p01.x; V[ky][1] = p01.y; V[ky][2] = p23.x; V[ky][3] = p23.y;
        }

        int pk = 0;
        #pragma unroll
        for (int ch = 0; ch < 4; ch++) {
            ull a0 = 0ull, a1 = 0ull;
            #pragma unroll
            for (int ky = 0; ky < 3; ky++) {
                const ull w0 = c_blob.w1[ch * 12 + ky * 4 + 0];   // LDC, uniform
                const ull w1 = c_blob.w1[ch * 12 + ky * 4 + 1];
                const ull w2 = c_blob.w1[ch * 12 + ky * 4 + 2];
                a0 = ffma2(V[ky][0], w0, a0);
                a0 = ffma2(V[ky][1], w1, a0);
                a0 = ffma2(V[ky][2], w2, a0);
                a1 = ffma2(V[ky][1], w0, a1);
                a1 = ffma2(V[ky][2], w1, a1);
                a1 = ffma2(V[ky][3], w2, a1);
            }
            float t0, bo0, t1, bo1;
            f2up(a0, t0, bo0); f2up(a1, t1, bo1);
            const float mx = fmaxf(fmaxf(t0, bo0), fmaxf(t1, bo1));
            const int a = min(max(__float2int_rn(mx), 0), 3);
            pk |= a << (8 * ch);
        }
        a1p[gi][(py + 1) * 16 + px + 1] = pk;
    }
    __syncthreads();

    // ---- phase 3: conv2 + pool + quant; weights via constant port --------
    if (t < 196) {
        const int gi = t / 98, v = t % 98;
        const int cp = v / 49, pp = v % 49;
        const int py = pp / 7, px = pp % 7;
        int q[4][4];
        #pragma unroll
        for (int r = 0; r < 4; r++) {
            int2 v0 = *(const int2*)&a1p[gi][(2 * py + r) * 16 + 2 * px];
            int2 v1 = *(const int2*)&a1p[gi][(2 * py + r) * 16 + 2 * px + 2];
            q[r][0] = v0.x; q[r][1] = v0.y; q[r][2] = v1.x; q[r][3] = v1.y;
        }
        const float s2v = c_blob.s2;
        unsigned int hv = 0;
        #pragma unroll
        for (int c2 = 0; c2 < 2; c2++) {
            const int ch = cp * 2 + c2;
            int wv[9];
            #pragma unroll
            for (int k = 0; k < 9; k++) wv[k] = c_blob.w2[ch * 12 + k];  // LDC, <=2-way
            int mx = -2147483647;
            #pragma unroll
            for (int wy = 0; wy < 2; wy++)
                #pragma unroll
                for (int wx = 0; wx < 2; wx++) {
                    int acc = 0;
                    #pragma unroll
                    for (int ky = 0; ky < 3; ky++)
                        #pragma unroll
                        for (int kx = 0; kx < 3; kx++)
                            acc = __dp4a(q[wy + ky][wx + kx], wv[ky * 3 + kx], acc);
                    mx = max(mx, acc);
                }
            const int a = min(max(__float2int_rn(s2v * (float)mx), 0), 3);
            hv |= (unsigned int)a << (8 * c2);
        }
        *(unsigned short*)((char*)&a2w[gi][0] + pp * 4 + cp * 2) = (unsigned short)hv;
    }
    __syncthreads();

    // ---- phase 4: FC, 20 tasks, 13 int4 weight loads (L1; divergent) -----
    if (t < 20) {
        const int gi = t / 10, o = t % 10;
        int acc = 0;
        const int4* wf4 = (const int4*)&g_wfpack[o * 52];
        #pragma unroll
        for (int j = 0; j < 13; j++) {
            int4 va = *(const int4*)&a2w[gi][4 * j];   // pads 49..51 are 0
            int4 wb = __ldg(wf4 + j);                  // pads are 0
            acc = __dp4a(va.x, wb.x, acc);
            acc = __dp4a(va.y, wb.y, acc);
            acc = __dp4a(va.z, wb.z, acc);
            acc = __dp4a(va.w, wb.w, acc);
        }
        out[(b0 + gi) * 10 + o] = c_blob.sf2 * (float)acc;
    }
}

extern "C" void kernel_launch(void* const* d_in, const int* in_sizes, int n_in,
                              void* d_out, int out_size) {
    const float* x  = (const float*)d_in[0];
    const float* w1 = (const float*)d_in[1];
    const float* w2 = (const float*)d_in[2];
    const float* wf = (const float*)d_in[3];
    float* out = (float*)d_out;
    const int B = in_sizes[0] / 784;

    prep_kernel<<<1, 256>>>(w1, w2, wf);

    // Stage -> constant bank. D2D async memcpy is graph-capturable and
    // allocation-free (both symbols are module globals).
    void *dst = nullptr, *src = nullptr;
    cudaGetSymbolAddress(&dst, c_blob);
    cudaGetSymbolAddress(&src, g_blob);
    cudaMemcpyAsync(dst, src, sizeof(WBlob), cudaMemcpyDeviceToDevice);

    net_kernel<<<B / 2, TPB>>>(x, out);
}